// round 4
// baseline (speedup 1.0000x reference)
#include <cuda_runtime.h>
#include <cuda_bf16.h>
#include <cstdint>

#define N_MAX   100000
#define E_MAX   3200000
#define C_DIM   40
#define F_DIM   128
#define NSHARD  8
#define CAPS    24
#define OVF_MAX 65536

// ---------------- scratch (device globals; no allocation) ----------------
__device__ int   g_is64;
__device__ int   g_cur[NSHARD * N_MAX];           // sharded cursors, strided
__device__ int   g_adj[(size_t)N_MAX * NSHARD * CAPS];
__device__ int   g_ovf_cnt;
__device__ int2  g_ovf[OVF_MAX];
__device__ float g_dinv[N_MAX];
__device__ __align__(16) float g_bufA[(size_t)N_MAX * C_DIM];
__device__ __align__(16) float g_bufB[(size_t)N_MAX * C_DIM];

__device__ __forceinline__ void red_add_v4(float* addr, float a, float b, float c, float d) {
    asm volatile("red.global.v4.f32.add [%0], {%1,%2,%3,%4};"
                 :: "l"(addr), "f"(a), "f"(b), "f"(c), "f"(d)
                 : "memory");
}

// ---------------- kernels ----------------

// Detect int64 vs int32 edge buffer (node ids < 2^31 -> int64 high words are 0).
__global__ void k_detect(const int* __restrict__ ei32, int E) {
    if (blockIdx.x == 0 && threadIdx.x == 0) {
        int n = E < 64 ? E : 64;
        int is64 = 1;
        for (int i = 0; i < n; ++i)
            if (ei32[2 * i + 1] != 0) { is64 = 0; break; }
        g_is64 = is64;
    }
}

__global__ void k_zero(int n8) {
    int i = blockIdx.x * blockDim.x + threadIdx.x;
    if (i < n8) g_cur[i] = 0;
    if (i == 0) g_ovf_cnt = 0;
}

// Fill bucket-CSR directly from the edge list (no histogram, no scan).
__global__ void k_fill(const int* __restrict__ ei32, int E) {
    int e = blockIdx.x * blockDim.x + threadIdx.x;
    if (e >= E) return;
    int r, c;
    if (g_is64) { r = ei32[2 * e]; c = ei32[2 * (E + e)]; }
    else        { r = ei32[e];     c = ei32[E + e]; }
    int sh = e & (NSHARD - 1);
    int p = atomicAdd(&g_cur[sh * N_MAX + c], 1);
    if (p < CAPS) {
        g_adj[((size_t)c * NSHARD + sh) * CAPS + p] = r;
    } else {
        int o = atomicAdd(&g_ovf_cnt, 1);
        if (o < OVF_MAX) g_ovf[o] = make_int2(r, c);
    }
}

// dinv[i] = rsqrt(1 + total in-degree)
__global__ void k_dinv(int N) {
    int i = blockIdx.x * blockDim.x + threadIdx.x;
    if (i >= N) return;
    int deg = 1;
#pragma unroll
    for (int sh = 0; sh < NSHARD; ++sh) deg += g_cur[sh * N_MAX + i];
    g_dinv[i] = rsqrtf((float)deg);
}

// Y[n, :] = X[n, :] @ W^T     (W is [C, F] row-major)
__global__ void k_gemm(const float* __restrict__ X, const float* __restrict__ W,
                       float* __restrict__ Y, int N) {
    __shared__ float ws[C_DIM * F_DIM];
    for (int i = threadIdx.x; i < C_DIM * F_DIM; i += blockDim.x) ws[i] = W[i];
    __syncthreads();

    int n = blockIdx.x * blockDim.x + threadIdx.x;
    if (n >= N) return;

    const float4* xp = (const float4*)(X + (size_t)n * F_DIM);
    float acc[C_DIM];
#pragma unroll
    for (int c = 0; c < C_DIM; ++c) acc[c] = 0.0f;

#pragma unroll 1
    for (int ch = 0; ch < 8; ++ch) {
        float4 xv[4];
#pragma unroll
        for (int j = 0; j < 4; ++j) xv[j] = xp[ch * 4 + j];
#pragma unroll
        for (int c = 0; c < C_DIM; ++c) {
            const float4* wp = (const float4*)(ws + c * F_DIM + ch * 16);
            float s = acc[c];
#pragma unroll
            for (int j = 0; j < 4; ++j) {
                float4 w = wp[j];
                s += xv[j].x * w.x + xv[j].y * w.y + xv[j].z * w.z + xv[j].w * w.w;
            }
            acc[c] = s;
        }
    }

    float4* yp = (float4*)(Y + (size_t)n * C_DIM);
#pragma unroll
    for (int k = 0; k < 10; ++k)
        yp[k] = make_float4(acc[4 * k], acc[4 * k + 1], acc[4 * k + 2], acc[4 * k + 3]);
}

// P = D * Y  (pre-scale so hop edge-weights become 1)
__global__ void k_scale(const float4* __restrict__ src, float4* __restrict__ dst,
                        int N) {
    int i = blockIdx.x * blockDim.x + threadIdx.x;
    if (i >= N * 10) return;
    float s = g_dinv[i / 10];
    float4 v = src[i];
    dst[i] = make_float4(s * v.x, s * v.y, s * v.z, s * v.w);
}

// One hop, gather form on pre-scaled data.
// dst[n] = dinv[n]^(2 or 1) * (src[n] + sum_{r in in(n)} src[r])
// 2 threads/node, 5 float4 each. Inner loop: pure adds (weight == 1).
__global__ void k_gather(const float4* __restrict__ src, float4* __restrict__ dst,
                         int N, int final_hop) {
    int t = blockIdx.x * blockDim.x + threadIdx.x;
    int n = t >> 1;
    if (n >= N) return;
    int part = (t & 1) * 5;

    float dn = g_dinv[n];
    float sc = final_hop ? dn : dn * dn;

    const float4* sp = src + (size_t)n * 10 + part;
    float4 a0 = sp[0], a1 = sp[1], a2 = sp[2], a3 = sp[3], a4 = sp[4];

#pragma unroll
    for (int sh = 0; sh < NSHARD; ++sh) {
        int m = g_cur[sh * N_MAX + n];
        m = m < CAPS ? m : CAPS;
        const int* ap = g_adj + ((size_t)n * NSHARD + sh) * CAPS;
        for (int k = 0; k < m; ++k) {
            int r = ap[k];
            const float4* v = src + (size_t)r * 10 + part;
            float4 v0 = v[0], v1 = v[1], v2 = v[2], v3 = v[3], v4 = v[4];
            a0.x += v0.x; a0.y += v0.y; a0.z += v0.z; a0.w += v0.w;
            a1.x += v1.x; a1.y += v1.y; a1.z += v1.z; a1.w += v1.w;
            a2.x += v2.x; a2.y += v2.y; a2.z += v2.z; a2.w += v2.w;
            a3.x += v3.x; a3.y += v3.y; a3.z += v3.z; a3.w += v3.w;
            a4.x += v4.x; a4.y += v4.y; a4.z += v4.z; a4.w += v4.w;
        }
    }

    float4* dp = dst + (size_t)n * 10 + part;
    dp[0] = make_float4(sc * a0.x, sc * a0.y, sc * a0.z, sc * a0.w);
    dp[1] = make_float4(sc * a1.x, sc * a1.y, sc * a1.z, sc * a1.w);
    dp[2] = make_float4(sc * a2.x, sc * a2.y, sc * a2.z, sc * a2.w);
    dp[3] = make_float4(sc * a3.x, sc * a3.y, sc * a3.z, sc * a3.w);
    dp[4] = make_float4(sc * a4.x, sc * a4.y, sc * a4.z, sc * a4.w);
}

// Overflow edges (rare): dst[c] += dinv[c]^(2 or 1) * src[r]
__global__ void k_ovf(const float4* __restrict__ src, float* __restrict__ dst,
                      int final_hop) {
    int cnt = g_ovf_cnt;
    if (cnt > OVF_MAX) cnt = OVF_MAX;
    for (int i = blockIdx.x * blockDim.x + threadIdx.x; i < cnt;
         i += gridDim.x * blockDim.x) {
        int2 rc = g_ovf[i];
        float dn = g_dinv[rc.y];
        float sc = final_hop ? dn : dn * dn;
        const float4* v = src + (size_t)rc.x * 10;
        float* d = dst + (size_t)rc.y * C_DIM;
#pragma unroll
        for (int k = 0; k < 10; ++k) {
            float4 x = v[k];
            red_add_v4(d + 4 * k, sc * x.x, sc * x.y, sc * x.z, sc * x.w);
        }
    }
}

// out[n, :] = log_softmax(src[n, :] + bias)
__global__ void k_lsm(const float* __restrict__ src, const float* __restrict__ bias,
                      float* __restrict__ out, int N) {
    int n = blockIdx.x * blockDim.x + threadIdx.x;
    if (n >= N) return;
    float z[C_DIM];
    const float4* s = (const float4*)(src + (size_t)n * C_DIM);
#pragma unroll
    for (int k = 0; k < 10; ++k) {
        float4 v = s[k];
        z[4 * k + 0] = v.x + bias[4 * k + 0];
        z[4 * k + 1] = v.y + bias[4 * k + 1];
        z[4 * k + 2] = v.z + bias[4 * k + 2];
        z[4 * k + 3] = v.w + bias[4 * k + 3];
    }
    float m = z[0];
#pragma unroll
    for (int c = 1; c < C_DIM; ++c) m = fmaxf(m, z[c]);
    float sum = 0.0f;
#pragma unroll
    for (int c = 0; c < C_DIM; ++c) sum += expf(z[c] - m);
    float l = m + logf(sum);
    float4* o = (float4*)(out + (size_t)n * C_DIM);
#pragma unroll
    for (int k = 0; k < 10; ++k)
        o[k] = make_float4(z[4 * k] - l, z[4 * k + 1] - l, z[4 * k + 2] - l, z[4 * k + 3] - l);
}

// ---------------- launch ----------------
extern "C" void kernel_launch(void* const* d_in, const int* in_sizes, int n_in,
                              void* d_out, int out_size) {
    const float* X    = (const float*)d_in[0];      // [N, 128]
    const float* W    = (const float*)d_in[1];      // [40, 128]
    const float* bias = (const float*)d_in[2];      // [40]
    const int*   ei   = (const int*)d_in[3];        // [2, E] int32 or int64
    (void)n_in;

    const int N = in_sizes[0] / F_DIM;
    const int E = in_sizes[3] / 2;
    float* out = (float*)d_out;
    (void)out_size;

    const int TB = 256;
    dim3 gN((N + TB - 1) / TB);
    dim3 gE((E + TB - 1) / TB);
    dim3 gZ((NSHARD * N + TB - 1) / TB);
    dim3 gV((N * 10 + TB - 1) / TB);
    dim3 gG((N * 2 + TB - 1) / TB);

    // bucket-CSR build (no hist, no scan)
    k_detect<<<1, 32>>>(ei, E);
    k_zero<<<gZ, TB>>>(NSHARD * N);
    k_fill<<<gE, TB>>>(ei, E);
    k_dinv<<<gN, TB>>>(N);

    // projection first (128 -> 40)
    k_gemm<<<gN, TB>>>(X, W, g_bufA, N);

    // pre-scale: bufB = D * Y
    k_scale<<<gV, TB>>>((const float4*)g_bufA, (float4*)g_bufB, N);

    // hop 1: bufA := D^2 (I+B) bufB   (= D * A_hat * Y)
    k_gather<<<gG, TB>>>((const float4*)g_bufB, (float4*)g_bufA, N, 0);
    k_ovf<<<16, TB>>>((const float4*)g_bufB, g_bufA, 0);

    // hop 2 (final): bufB := D (I+B) bufA  (= A_hat^2 * Y)
    k_gather<<<gG, TB>>>((const float4*)g_bufA, (float4*)g_bufB, N, 1);
    k_ovf<<<16, TB>>>((const float4*)g_bufA, g_bufB, 1);

    // bias + log_softmax
    k_lsm<<<gN, TB>>>(g_bufB, bias, out, N);
}